// round 2
// baseline (speedup 1.0000x reference)
#include <cuda_runtime.h>

// LinearSelfAttention — restructured:
//   PH  = P @ H                      (B, 257, 2049)
//   A   = PH[:, :2048] @ H[:, :2048]^T   (mask folded into K-truncation)
//   A2  = A @ Q                      (B, 257, 257)
//   out = H + (A2 @ H) / 2048
//
// Scratch as __device__ globals (allocation-free rule).

#define BATCH 16
#define DP1   257
#define NP1   2049
#define NMASK 2048

__device__ float g_PH[BATCH * DP1 * NP1];   // 33.7 MB
__device__ float g_A [BATCH * DP1 * DP1];   // 4.2 MB
__device__ float g_A2[BATCH * DP1 * DP1];   // 4.2 MB

#define BM 64
#define BN 64
#define BK 16
#define TM 4
#define TN 4

// Generic batched SGEMM: C = scale * (A @ B or A @ B^T) [+ addsrc]
// A: M x K row-major (lda). B: K x N row-major (ldb) if !TRANS_B,
// else N x K row-major (ldb). C: M x N row-major (ldc).
template<bool TRANS_B>
__global__ void __launch_bounds__(256)
sgemm_kernel(const float* __restrict__ A, const float* __restrict__ B,
             float* __restrict__ C, const float* __restrict__ addsrc,
             float scale,
             int M, int N, int K,
             int lda, int ldb, int ldc,
             long sA, long sB, long sC, long sAdd)
{
    const int bz = blockIdx.z;
    A += (long)bz * sA;
    B += (long)bz * sB;
    C += (long)bz * sC;
    const float* addp = addsrc ? (addsrc + (long)bz * sAdd) : nullptr;

    const int bm = blockIdx.y * BM;
    const int bn = blockIdx.x * BN;

    __shared__ float As[BK][BM + 4];
    __shared__ float Bs[BK][BN + 4];

    const int tid = threadIdx.x;
    const int tx = tid & 15;     // 0..15
    const int ty = tid >> 4;     // 0..15

    float acc[TM][TN];
    #pragma unroll
    for (int i = 0; i < TM; i++)
        #pragma unroll
        for (int j = 0; j < TN; j++)
            acc[i][j] = 0.f;

    // A-tile loader mapping: each thread loads 4 consecutive k for one row m
    const int m_a  = tid >> 2;        // 0..63
    const int kq_a = (tid & 3) * 4;   // 0,4,8,12
    // B-tile loader mapping (NN): each thread loads 4 consecutive n for one k
    const int k_b  = tid >> 4;        // 0..15
    const int n0_b = (tid & 15) * 4;  // 0..60

    for (int k0 = 0; k0 < K; k0 += BK) {
        // --- load A tile: As[k][m] = A[(bm+m)*lda + k0+k]
        {
            const int grow = bm + m_a;
            #pragma unroll
            for (int i = 0; i < 4; i++) {
                const int kk = kq_a + i;
                float v = 0.f;
                if (grow < M && (k0 + kk) < K)
                    v = A[(long)grow * lda + (k0 + kk)];
                As[kk][m_a] = v;
            }
        }
        // --- load B tile: Bs[k][n]
        if (TRANS_B) {
            const int grow = bn + m_a;
            #pragma unroll
            for (int i = 0; i < 4; i++) {
                const int kk = kq_a + i;
                float v = 0.f;
                if (grow < N && (k0 + kk) < K)
                    v = B[(long)grow * ldb + (k0 + kk)];
                Bs[kk][m_a] = v;
            }
        } else {
            const int gk = k0 + k_b;
            #pragma unroll
            for (int j = 0; j < 4; j++) {
                const int nn = n0_b + j;
                float v = 0.f;
                if (gk < K && (bn + nn) < N)
                    v = B[(long)gk * ldb + (bn + nn)];
                Bs[k_b][nn] = v;
            }
        }
        __syncthreads();

        #pragma unroll
        for (int k = 0; k < BK; k++) {
            float a[TM], b[TN];
            #pragma unroll
            for (int i = 0; i < TM; i++) a[i] = As[k][ty * TM + i];
            #pragma unroll
            for (int j = 0; j < TN; j++) b[j] = Bs[k][tx * TN + j];
            #pragma unroll
            for (int i = 0; i < TM; i++)
                #pragma unroll
                for (int j = 0; j < TN; j++)
                    acc[i][j] += a[i] * b[j];
        }
        __syncthreads();
    }

    #pragma unroll
    for (int i = 0; i < TM; i++) {
        const int row = bm + ty * TM + i;
        if (row >= M) continue;
        #pragma unroll
        for (int j = 0; j < TN; j++) {
            const int col = bn + tx * TN + j;
            if (col >= N) continue;
            float v = acc[i][j] * scale;
            if (addp) v += addp[(long)row * ldc + col];
            C[(long)row * ldc + col] = v;
        }
    }
}

extern "C" void kernel_launch(void* const* d_in, const int* in_sizes, int n_in,
                              void* d_out, int out_size)
{
    const float* H = (const float*)d_in[0];   // (16, 257, 2049)
    const float* P = (const float*)d_in[1];   // (257, 257)
    const float* Q = (const float*)d_in[2];   // (257, 257)
    float* out = (float*)d_out;               // (16, 257, 2049)

    void *pPH = nullptr, *pA = nullptr, *pA2 = nullptr;
    cudaGetSymbolAddress(&pPH, g_PH);
    cudaGetSymbolAddress(&pA,  g_A);
    cudaGetSymbolAddress(&pA2, g_A2);
    float* PH = (float*)pPH;
    float* A  = (float*)pA;
    float* A2 = (float*)pA2;

    const long sH  = (long)DP1 * NP1;   // 526593
    const long sDD = (long)DP1 * DP1;   // 66049

    dim3 block(256);
    dim3 gridWide((NP1 + BN - 1) / BN, (DP1 + BM - 1) / BM, BATCH);  // 33 x 5 x 16
    dim3 gridSq  ((DP1 + BN - 1) / BN, (DP1 + BM - 1) / BM, BATCH);  //  5 x 5 x 16

    // Step 1: PH[b] = P @ H[b]   (M=257, N=2049, K=257)
    sgemm_kernel<false><<<gridWide, block>>>(
        P, H, PH, nullptr, 1.0f,
        DP1, NP1, DP1,
        DP1, NP1, NP1,
        0, sH, sH, 0);

    // Step 2: A[b] = PH[b][:, :2048] @ H[b][:, :2048]^T  (M=257, N=257, K=2048)
    // (mask M: dropping s = n = 2048 from the contraction == zeroing last row of HtQH)
    sgemm_kernel<true><<<gridSq, block>>>(
        PH, H, A, nullptr, 1.0f,
        DP1, DP1, NMASK,
        NP1, NP1, DP1,
        sH, sH, sDD, 0);

    // Step 3: A2[b] = A[b] @ Q  (M=257, N=257, K=257)
    sgemm_kernel<false><<<gridSq, block>>>(
        A, Q, A2, nullptr, 1.0f,
        DP1, DP1, DP1,
        DP1, DP1, DP1,
        sDD, 0, sDD, 0);

    // Step 4: out[b] = H[b] + (A2[b] @ H[b]) / 2048  (M=257, N=2049, K=257)
    sgemm_kernel<false><<<gridWide, block>>>(
        A2, H, out, H, 1.0f / (float)NMASK,
        DP1, NP1, DP1,
        DP1, NP1, NP1,
        sDD, sH, sH, sH);
}

// round 3
// speedup vs baseline: 3.7052x; 3.7052x over previous
#include <cuda_runtime.h>
#include <cuda_bf16.h>
#include <cstdint>

// LinearSelfAttention restructured (mask folded into K-truncation):
//   PH  = P @ H                         (B, 257, 2049)
//   A   = PH[:, :2048] @ H[:, :2048]^T  (B, 257, 257)
//   A2  = A @ Q                         (B, 257, 257)
//   out = H + (A2 @ H) / 2048
// All GEMMs in bf16 mma.sync (fp32 accum), NT form via transposed copies.

#define BATCH 16
#define D_REAL 257
#define N_REAL 2049
#define HSTR   (257L * 2049L)

#define DP 384      // padded d used as M/N (multiple of 128)
#define DK 288      // padded d used as K   (multiple of 32)
#define NP 2176     // padded n             (multiple of 128)

// zero-initialized device scratch (allocation-free rule)
__device__ __nv_bfloat16 g_Hb [BATCH * DP * NP];  // H  as [d][n] bf16
__device__ __nv_bfloat16 g_HbT[BATCH * NP * DP];  // H^T as [n][d] bf16
__device__ __nv_bfloat16 g_Pb [DP * DK];
__device__ __nv_bfloat16 g_QbT[DP * DK];          // Q^T
__device__ __nv_bfloat16 g_PHb[BATCH * DP * NP];
__device__ __nv_bfloat16 g_Ab [BATCH * DP * DP];
__device__ __nv_bfloat16 g_A2b[BATCH * DP * DP];

// ---------------------------------------------------------------- converts

__global__ void conv_H(const float* __restrict__ H,
                       __nv_bfloat16* __restrict__ Hb,
                       __nv_bfloat16* __restrict__ HbT)
{
    __shared__ float t[32][33];
    const int b  = blockIdx.z;
    const int n0 = blockIdx.x * 32;
    const int d0 = blockIdx.y * 32;
    const int tx = threadIdx.x, ty = threadIdx.y;
    const float* Hp = H + (long)b * HSTR;

    #pragma unroll
    for (int i = 0; i < 4; i++) {
        int d = d0 + ty + i * 8;
        int n = n0 + tx;
        float v = 0.f;
        if (d < D_REAL && n < N_REAL) v = Hp[(long)d * N_REAL + n];
        t[ty + i * 8][tx] = v;
    }
    __syncthreads();

    __nv_bfloat16* Hbp  = Hb  + (long)b * DP * NP;
    __nv_bfloat16* HbTp = HbT + (long)b * NP * DP;
    #pragma unroll
    for (int i = 0; i < 4; i++) {
        int d = d0 + ty + i * 8;
        int n = n0 + tx;
        Hbp[(long)d * NP + n] = __float2bfloat16(t[ty + i * 8][tx]);
    }
    #pragma unroll
    for (int i = 0; i < 4; i++) {
        int n = n0 + ty + i * 8;
        int d = d0 + tx;
        HbTp[(long)n * DP + d] = __float2bfloat16(t[tx][ty + i * 8]);
    }
}

__global__ void conv_P(const float* __restrict__ P, __nv_bfloat16* __restrict__ Pb)
{
    int idx = blockIdx.x * blockDim.x + threadIdx.x;
    if (idx >= DP * DK) return;
    int r = idx / DK, c = idx % DK;
    float v = (r < D_REAL && c < D_REAL) ? P[r * D_REAL + c] : 0.f;
    Pb[idx] = __float2bfloat16(v);
}

__global__ void conv_QT(const float* __restrict__ Q, __nv_bfloat16* __restrict__ QbT)
{
    int idx = blockIdx.x * blockDim.x + threadIdx.x;
    if (idx >= DP * DK) return;
    int n = idx / DK, k = idx % DK;
    float v = (n < D_REAL && k < D_REAL) ? Q[k * D_REAL + n] : 0.f;
    QbT[idx] = __float2bfloat16(v);
}

// ---------------------------------------------------------------- GEMM NT

__device__ __forceinline__ void cp16(void* dst, const void* src)
{
    uint32_t d = (uint32_t)__cvta_generic_to_shared(dst);
    asm volatile("cp.async.cg.shared.global [%0], [%1], 16;\n" :: "r"(d), "l"(src));
}

__device__ __forceinline__ void mma16816(float* d, const uint32_t* a, const uint32_t* b)
{
    asm volatile(
        "mma.sync.aligned.m16n8k16.row.col.f32.bf16.bf16.f32 "
        "{%0,%1,%2,%3}, {%4,%5,%6,%7}, {%8,%9}, {%0,%1,%2,%3};"
        : "+f"(d[0]), "+f"(d[1]), "+f"(d[2]), "+f"(d[3])
        : "r"(a[0]), "r"(a[1]), "r"(a[2]), "r"(a[3]), "r"(b[0]), "r"(b[1]));
}

// C[M,N] = scale * A[M,K] @ B[N,K]^T  (both row-major over K)
// EPI=0: store bf16 to Cb (padded, unguarded)
// EPI=1: out fp32 = Hadd + acc*scale, guarded to 257x2049
template<int EPI>
__global__ void __launch_bounds__(256)
gemm_nt(const __nv_bfloat16* __restrict__ A,
        const __nv_bfloat16* __restrict__ B,
        __nv_bfloat16* __restrict__ Cb,
        float* __restrict__ Cf,
        const float* __restrict__ Hadd,
        int K, int lda, int ldb, int ldc,
        long sA, long sB, long sC, float scale)
{
    const int bz = blockIdx.z;
    A += (long)bz * sA;
    B += (long)bz * sB;

    const int bm = blockIdx.y * 128;
    const int bn = blockIdx.x * 128;

    __shared__ __nv_bfloat16 As[2][128 * 40];   // pitch 40 bf16 (20 words)
    __shared__ __nv_bfloat16 Bs[2][128 * 40];

    const int tid  = threadIdx.x;
    const int lane = tid & 31;
    const int wid  = tid >> 5;
    const int g    = lane >> 2;
    const int tig  = lane & 3;
    const int wm   = (wid >> 2) * 64;   // 2 warps in m
    const int wn   = (wid & 3) * 32;    // 4 warps in n

    float acc[4][4][4];
    #pragma unroll
    for (int i = 0; i < 4; i++)
        #pragma unroll
        for (int j = 0; j < 4; j++)
            #pragma unroll
            for (int r = 0; r < 4; r++) acc[i][j][r] = 0.f;

    auto load_stage = [&](int st, int k0) {
        #pragma unroll
        for (int i = 0; i < 2; i++) {
            int ch  = tid + i * 256;          // 512 chunks of 16B per tile
            int row = ch >> 2;
            int kq  = (ch & 3) * 8;
            cp16(&As[st][row * 40 + kq], A + (long)(bm + row) * lda + k0 + kq);
            cp16(&Bs[st][row * 40 + kq], B + (long)(bn + row) * ldb + k0 + kq);
        }
        asm volatile("cp.async.commit_group;");
    };

    const int nk = K / 32;
    load_stage(0, 0);

    for (int kt = 0; kt < nk; kt++) {
        if (kt + 1 < nk) {
            load_stage((kt + 1) & 1, (kt + 1) * 32);
            asm volatile("cp.async.wait_group 1;");
        } else {
            asm volatile("cp.async.wait_group 0;");
        }
        __syncthreads();

        const uint32_t* aw = (const uint32_t*)As[kt & 1];
        const uint32_t* bw = (const uint32_t*)Bs[kt & 1];

        #pragma unroll
        for (int kk = 0; kk < 2; kk++) {     // two k16 steps per BK=32
            const int kw = kk * 8 + tig;
            uint32_t af[4][4], bfr[4][2];
            #pragma unroll
            for (int mi = 0; mi < 4; mi++) {
                int r = wm + mi * 16 + g;
                af[mi][0] = aw[r * 20 + kw];
                af[mi][1] = aw[(r + 8) * 20 + kw];
                af[mi][2] = aw[r * 20 + kw + 4];
                af[mi][3] = aw[(r + 8) * 20 + kw + 4];
            }
            #pragma unroll
            for (int ni = 0; ni < 4; ni++) {
                int n = wn + ni * 8 + g;
                bfr[ni][0] = bw[n * 20 + kw];
                bfr[ni][1] = bw[n * 20 + kw + 4];
            }
            #pragma unroll
            for (int mi = 0; mi < 4; mi++)
                #pragma unroll
                for (int ni = 0; ni < 4; ni++)
                    mma16816(acc[mi][ni], af[mi], bfr[ni]);
        }
        __syncthreads();
    }

    if (EPI == 0) {
        __nv_bfloat16* Cp = Cb + (long)bz * sC;
        #pragma unroll
        for (int mi = 0; mi < 4; mi++) {
            int r0 = bm + wm + mi * 16 + g;
            #pragma unroll
            for (int ni = 0; ni < 4; ni++) {
                int c = bn + wn + ni * 8 + tig * 2;
                __nv_bfloat162 v01, v23;
                v01.x = __float2bfloat16(acc[mi][ni][0] * scale);
                v01.y = __float2bfloat16(acc[mi][ni][1] * scale);
                v23.x = __float2bfloat16(acc[mi][ni][2] * scale);
                v23.y = __float2bfloat16(acc[mi][ni][3] * scale);
                *(__nv_bfloat162*)&Cp[(long)r0 * ldc + c]       = v01;
                *(__nv_bfloat162*)&Cp[(long)(r0 + 8) * ldc + c] = v23;
            }
        }
    } else {
        const float* Hp = Hadd + (long)bz * HSTR;
        float*       Op = Cf   + (long)bz * HSTR;
        #pragma unroll
        for (int mi = 0; mi < 4; mi++) {
            int r0 = bm + wm + mi * 16 + g;
            #pragma unroll
            for (int ni = 0; ni < 4; ni++) {
                int c = bn + wn + ni * 8 + tig * 2;
                #pragma unroll
                for (int half = 0; half < 2; half++) {
                    int r = r0 + half * 8;
                    if (r < D_REAL) {
                        if (c < N_REAL) {
                            long idx = (long)r * N_REAL + c;
                            Op[idx] = Hp[idx] + acc[mi][ni][half * 2 + 0] * scale;
                        }
                        if (c + 1 < N_REAL) {
                            long idx = (long)r * N_REAL + c + 1;
                            Op[idx] = Hp[idx] + acc[mi][ni][half * 2 + 1] * scale;
                        }
                    }
                }
            }
        }
    }
}

// ---------------------------------------------------------------- launch

extern "C" void kernel_launch(void* const* d_in, const int* in_sizes, int n_in,
                              void* d_out, int out_size)
{
    const float* H = (const float*)d_in[0];   // (16, 257, 2049)
    const float* P = (const float*)d_in[1];   // (257, 257)
    const float* Q = (const float*)d_in[2];   // (257, 257)
    float* out = (float*)d_out;

    void *pHb, *pHbT, *pPb, *pQbT, *pPHb, *pAb, *pA2b;
    cudaGetSymbolAddress(&pHb,  g_Hb);
    cudaGetSymbolAddress(&pHbT, g_HbT);
    cudaGetSymbolAddress(&pPb,  g_Pb);
    cudaGetSymbolAddress(&pQbT, g_QbT);
    cudaGetSymbolAddress(&pPHb, g_PHb);
    cudaGetSymbolAddress(&pAb,  g_Ab);
    cudaGetSymbolAddress(&pA2b, g_A2b);
    __nv_bfloat16* Hb  = (__nv_bfloat16*)pHb;
    __nv_bfloat16* HbT = (__nv_bfloat16*)pHbT;
    __nv_bfloat16* Pb  = (__nv_bfloat16*)pPb;
    __nv_bfloat16* QbT = (__nv_bfloat16*)pQbT;
    __nv_bfloat16* PHb = (__nv_bfloat16*)pPHb;
    __nv_bfloat16* Ab  = (__nv_bfloat16*)pAb;
    __nv_bfloat16* A2b = (__nv_bfloat16*)pA2b;

    const long sHN = (long)DP * NP;   // Hb / PHb batch stride
    const long sNT = (long)NP * DP;   // HbT batch stride
    const long sDD = (long)DP * DP;   // Ab / A2b batch stride

    // converts
    conv_H <<<dim3(NP / 32, DP / 32, BATCH), dim3(32, 8)>>>(H, Hb, HbT);
    conv_P <<<(DP * DK + 255) / 256, 256>>>(P, Pb);
    conv_QT<<<(DP * DK + 255) / 256, 256>>>(Q, QbT);

    dim3 blk(256);
    dim3 gWide(NP / 128, DP / 128, BATCH);   // 17 x 3 x 16
    dim3 gSq  (DP / 128, DP / 128, BATCH);   //  3 x 3 x 16

    // 1) PH[b] = P @ H[b]        : A=Pb [384x288], B=HbT [2176x384 rows over k=288]
    gemm_nt<0><<<gWide, blk>>>(Pb, HbT, PHb, nullptr, nullptr,
                               DK, DK, DP, NP, 0, sNT, sHN, 1.f);

    // 2) A[b] = PH[b][:, :2048] @ H[b][:, :2048]^T   (mask == K truncation)
    gemm_nt<0><<<gSq, blk>>>(PHb, Hb, Ab, nullptr, nullptr,
                             2048, NP, NP, DP, sHN, sHN, sDD, 1.f);

    // 3) A2[b] = A[b] @ Q        : B = QbT
    gemm_nt<0><<<gSq, blk>>>(Ab, QbT, A2b, nullptr, nullptr,
                             DK, DP, DK, DP, sDD, 0, sDD, 1.f);

    // 4) out[b] = H[b] + (A2[b] @ H[b]) / 2048
    gemm_nt<1><<<gWide, blk>>>(A2b, HbT, nullptr, out, H,
                               DK, DP, DP, 0, sDD, sNT, 0, 1.f / 2048.f);
}

// round 4
// speedup vs baseline: 4.4471x; 1.2002x over previous
#include <cuda_runtime.h>
#include <cuda_bf16.h>
#include <cstdint>

// LinearSelfAttention, fully factored:
//   G  = H[:, :2048] @ H[:, :2048]^T     (mask == K-truncation; G symmetric)
//   T1 = P @ G
//   A2 = T1 @ Q
//   out = H + (A2 @ H) / 2048
// bf16 mma.sync GEMMs (fp32 accum), NT form, 3-stage cp.async pipeline.

#define BATCH 16
#define D_REAL 257
#define N_REAL 2049
#define HSTR   (257L * 2049L)

#define DP 384      // padded d as M/N
#define DK 288      // padded d as K
#define NP 2176     // padded n
#define STAGES 3

__device__ __align__(256) __nv_bfloat16 g_Hb [BATCH * DP * NP];  // H  [d][n]
__device__ __align__(256) __nv_bfloat16 g_HbT[BATCH * NP * DP];  // H^T [n][d]
__device__ __align__(256) __nv_bfloat16 g_Pb [DP * DK];
__device__ __align__(256) __nv_bfloat16 g_QbT[DP * DK];          // Q^T
__device__ __align__(256) __nv_bfloat16 g_S1 [BATCH * DP * DP];
__device__ __align__(256) __nv_bfloat16 g_S2 [BATCH * DP * DP];

// ---------------------------------------------------------------- converts

__global__ void conv_H(const float* __restrict__ H,
                       __nv_bfloat16* __restrict__ Hb,
                       __nv_bfloat16* __restrict__ HbT)
{
    __shared__ float t[32][33];
    const int b  = blockIdx.z;
    const int n0 = blockIdx.x * 32;
    const int d0 = blockIdx.y * 32;
    const int tx = threadIdx.x, ty = threadIdx.y;
    const float* Hp = H + (long)b * HSTR;

    #pragma unroll
    for (int i = 0; i < 4; i++) {
        int d = d0 + ty + i * 8;
        int n = n0 + tx;
        float v = 0.f;
        if (d < D_REAL && n < N_REAL) v = Hp[(long)d * N_REAL + n];
        t[ty + i * 8][tx] = v;
    }
    __syncthreads();

    __nv_bfloat16* Hbp  = Hb  + (long)b * DP * NP;
    __nv_bfloat16* HbTp = HbT + (long)b * NP * DP;
    #pragma unroll
    for (int i = 0; i < 4; i++) {
        int d = d0 + ty + i * 8;
        int n = n0 + tx;
        Hbp[(long)d * NP + n] = __float2bfloat16(t[ty + i * 8][tx]);
    }
    #pragma unroll
    for (int i = 0; i < 4; i++) {
        int n = n0 + ty + i * 8;
        int d = d0 + tx;
        HbTp[(long)n * DP + d] = __float2bfloat16(t[tx][ty + i * 8]);
    }
}

__global__ void conv_P(const float* __restrict__ P, __nv_bfloat16* __restrict__ Pb)
{
    int idx = blockIdx.x * blockDim.x + threadIdx.x;
    if (idx >= DP * DK) return;
    int r = idx / DK, c = idx % DK;
    float v = (r < D_REAL && c < D_REAL) ? P[r * D_REAL + c] : 0.f;
    Pb[idx] = __float2bfloat16(v);
}

__global__ void conv_QT(const float* __restrict__ Q, __nv_bfloat16* __restrict__ QbT)
{
    int idx = blockIdx.x * blockDim.x + threadIdx.x;
    if (idx >= DP * DK) return;
    int n = idx / DK, k = idx % DK;
    float v = (n < D_REAL && k < D_REAL) ? Q[k * D_REAL + n] : 0.f;
    QbT[idx] = __float2bfloat16(v);
}

// ---------------------------------------------------------------- GEMM NT

__device__ __forceinline__ void cp16(void* dst, const void* src)
{
    uint32_t d = (uint32_t)__cvta_generic_to_shared(dst);
    asm volatile("cp.async.cg.shared.global [%0], [%1], 16;\n" :: "r"(d), "l"(src));
}

__device__ __forceinline__ void mma16816(float* d, const uint32_t* a, const uint32_t* b)
{
    asm volatile(
        "mma.sync.aligned.m16n8k16.row.col.f32.bf16.bf16.f32 "
        "{%0,%1,%2,%3}, {%4,%5,%6,%7}, {%8,%9}, {%0,%1,%2,%3};"
        : "+f"(d[0]), "+f"(d[1]), "+f"(d[2]), "+f"(d[3])
        : "r"(a[0]), "r"(a[1]), "r"(a[2]), "r"(a[3]), "r"(b[0]), "r"(b[1]));
}

// C[M,N] = scale * A[M,K] @ B[N,K]^T, tile BM = MI*32 x 128, 3-stage pipeline.
// EPI=0: store bf16 to Cb (padded, unguarded).
// EPI=1: fp32 out = Hadd + acc*scale, guarded to 257x2049.
template<int MI, int EPI>
__global__ void __launch_bounds__(256)
gemm_nt(const __nv_bfloat16* __restrict__ A,
        const __nv_bfloat16* __restrict__ B,
        __nv_bfloat16* __restrict__ Cb,
        float* __restrict__ Cf,
        const float* __restrict__ Hadd,
        int K, int lda, int ldb, int ldc,
        long sA, long sB, long sC, float scale)
{
    constexpr int BM = MI * 32;
    const int bz = blockIdx.z;
    A += (long)bz * sA;
    B += (long)bz * sB;

    const int bm = blockIdx.y * BM;
    const int bn = blockIdx.x * 128;

    extern __shared__ __nv_bfloat16 sm[];
    __nv_bfloat16* As = sm;                         // [STAGES][BM*40]
    __nv_bfloat16* Bs = sm + STAGES * BM * 40;      // [STAGES][128*40]

    const int tid  = threadIdx.x;
    const int lane = tid & 31;
    const int wid  = tid >> 5;
    const int g    = lane >> 2;
    const int tig  = lane & 3;
    const int wm   = (wid >> 2) * (MI * 16);  // 2 warps in m
    const int wn   = (wid & 3) * 32;          // 4 warps in n

    float acc[MI][4][4];
    #pragma unroll
    for (int i = 0; i < MI; i++)
        #pragma unroll
        for (int j = 0; j < 4; j++)
            #pragma unroll
            for (int r = 0; r < 4; r++) acc[i][j][r] = 0.f;

    auto load_stage = [&](int st, int k0) {
        // A tile: BM*4 chunks of 16B
        #pragma unroll
        for (int i = 0; i < BM * 4 / 256; i++) {
            int ch  = tid + i * 256;
            int row = ch >> 2;
            int kq  = (ch & 3) * 8;
            cp16(&As[st * BM * 40 + row * 40 + kq],
                 A + (long)(bm + row) * lda + k0 + kq);
        }
        // B tile: 512 chunks
        #pragma unroll
        for (int i = 0; i < 2; i++) {
            int ch  = tid + i * 256;
            int row = ch >> 2;
            int kq  = (ch & 3) * 8;
            cp16(&Bs[st * 128 * 40 + row * 40 + kq],
                 B + (long)(bn + row) * ldb + k0 + kq);
        }
    };

    const int nk = K / 32;
    load_stage(0, 0);
    asm volatile("cp.async.commit_group;");
    load_stage(1, 32);
    asm volatile("cp.async.commit_group;");

    for (int kt = 0; kt < nk; kt++) {
        if (kt + 2 < nk) load_stage((kt + 2) % STAGES, (kt + 2) * 32);
        asm volatile("cp.async.commit_group;");
        asm volatile("cp.async.wait_group %0;" :: "n"(STAGES - 1));
        __syncthreads();

        const uint32_t* aw = (const uint32_t*)(As + (kt % STAGES) * BM * 40);
        const uint32_t* bw = (const uint32_t*)(Bs + (kt % STAGES) * 128 * 40);

        #pragma unroll
        for (int kk = 0; kk < 2; kk++) {
            const int kw = kk * 8 + tig;
            uint32_t af[MI][4], bfr[4][2];
            #pragma unroll
            for (int mi = 0; mi < MI; mi++) {
                int r = wm + mi * 16 + g;
                af[mi][0] = aw[r * 20 + kw];
                af[mi][1] = aw[(r + 8) * 20 + kw];
                af[mi][2] = aw[r * 20 + kw + 4];
                af[mi][3] = aw[(r + 8) * 20 + kw + 4];
            }
            #pragma unroll
            for (int ni = 0; ni < 4; ni++) {
                int n = wn + ni * 8 + g;
                bfr[ni][0] = bw[n * 20 + kw];
                bfr[ni][1] = bw[n * 20 + kw + 4];
            }
            #pragma unroll
            for (int mi = 0; mi < MI; mi++)
                #pragma unroll
                for (int ni = 0; ni < 4; ni++)
                    mma16816(acc[mi][ni], af[mi], bfr[ni]);
        }
        __syncthreads();
    }

    if (EPI == 0) {
        __nv_bfloat16* Cp = Cb + (long)bz * sC;
        #pragma unroll
        for (int mi = 0; mi < MI; mi++) {
            int r0 = bm + wm + mi * 16 + g;
            #pragma unroll
            for (int ni = 0; ni < 4; ni++) {
                int c = bn + wn + ni * 8 + tig * 2;
                __nv_bfloat162 v01, v23;
                v01.x = __float2bfloat16(acc[mi][ni][0] * scale);
                v01.y = __float2bfloat16(acc[mi][ni][1] * scale);
                v23.x = __float2bfloat16(acc[mi][ni][2] * scale);
                v23.y = __float2bfloat16(acc[mi][ni][3] * scale);
                *(__nv_bfloat162*)&Cp[(long)r0 * ldc + c]       = v01;
                *(__nv_bfloat162*)&Cp[(long)(r0 + 8) * ldc + c] = v23;
            }
        }
    } else {
        const float* Hp = Hadd + (long)bz * HSTR;
        float*       Op = Cf   + (long)bz * HSTR;
        #pragma unroll
        for (int mi = 0; mi < MI; mi++) {
            int r0 = bm + wm + mi * 16 + g;
            #pragma unroll
            for (int ni = 0; ni < 4; ni++) {
                int c = bn + wn + ni * 8 + tig * 2;
                #pragma unroll
                for (int half = 0; half < 2; half++) {
                    int r = r0 + half * 8;
                    if (r < D_REAL) {
                        if (c < N_REAL) {
                            long idx = (long)r * N_REAL + c;
                            Op[idx] = Hp[idx] + acc[mi][ni][half * 2 + 0] * scale;
                        }
                        if (c + 1 < N_REAL) {
                            long idx = (long)r * N_REAL + c + 1;
                            Op[idx] = Hp[idx] + acc[mi][ni][half * 2 + 1] * scale;
                        }
                    }
                }
            }
        }
    }
}

// ---------------------------------------------------------------- launch

extern "C" void kernel_launch(void* const* d_in, const int* in_sizes, int n_in,
                              void* d_out, int out_size)
{
    const float* H = (const float*)d_in[0];   // (16, 257, 2049)
    const float* P = (const float*)d_in[1];   // (257, 257)
    const float* Q = (const float*)d_in[2];   // (257, 257)
    float* out = (float*)d_out;

    void *pHb, *pHbT, *pPb, *pQbT, *pS1, *pS2;
    cudaGetSymbolAddress(&pHb,  g_Hb);
    cudaGetSymbolAddress(&pHbT, g_HbT);
    cudaGetSymbolAddress(&pPb,  g_Pb);
    cudaGetSymbolAddress(&pQbT, g_QbT);
    cudaGetSymbolAddress(&pS1,  g_S1);
    cudaGetSymbolAddress(&pS2,  g_S2);
    __nv_bfloat16* Hb  = (__nv_bfloat16*)pHb;
    __nv_bfloat16* HbT = (__nv_bfloat16*)pHbT;
    __nv_bfloat16* Pb  = (__nv_bfloat16*)pPb;
    __nv_bfloat16* QbT = (__nv_bfloat16*)pQbT;
    __nv_bfloat16* S1  = (__nv_bfloat16*)pS1;
    __nv_bfloat16* S2  = (__nv_bfloat16*)pS2;

    const long sHN = (long)DP * NP;
    const long sNT = (long)NP * DP;
    const long sDD = (long)DP * DP;

    conv_H <<<dim3(NP / 32, DP / 32, BATCH), dim3(32, 8)>>>(H, Hb, HbT);
    conv_P <<<(DP * DK + 255) / 256, 256>>>(P, Pb);
    conv_QT<<<(DP * DK + 255) / 256, 256>>>(Q, QbT);

    dim3 blk(256);
    dim3 gSq  (DP / 128, DP / 64, BATCH);    // 3 x 6 x 16 = 288
    dim3 gWide(NP / 128, DP / 64, BATCH);    // 17 x 6 x 16 = 1632
    const int smem = STAGES * (64 + 128) * 40 * sizeof(__nv_bfloat16);  // 46080

    // 1) G[b] = H[:, :2048] @ H[:, :2048]^T   (mask == K-truncation)
    gemm_nt<2, 0><<<gSq, blk, smem>>>(Hb, Hb, S1, nullptr, nullptr,
                                      2048, NP, NP, DP, sHN, sHN, sDD, 1.f);

    // 2) T1[b] = P @ G[b]   (G symmetric -> use G directly as B-operand)
    gemm_nt<2, 0><<<gSq, blk, smem>>>(Pb, S1, S2, nullptr, nullptr,
                                      DK, DK, DP, DP, 0, sDD, sDD, 1.f);

    // 3) A2[b] = T1[b] @ Q
    gemm_nt<2, 0><<<gSq, blk, smem>>>(S2, QbT, S1, nullptr, nullptr,
                                      DK, DP, DK, DP, sDD, 0, sDD, 1.f);

    // 4) out[b] = H[b] + (A2[b] @ H[b]) / 2048
    gemm_nt<2, 1><<<gWide, blk, smem>>>(S1, HbT, nullptr, out, H,
                                        DK, DP, DP, 0, sDD, sNT, 0, 1.f / 2048.f);
}

// round 9
// speedup vs baseline: 5.3467x; 1.2023x over previous
#include <cuda_runtime.h>
#include <cuda_bf16.h>
#include <cstdint>

// LinearSelfAttention, factored:
//   G  = H[:, :2048] @ H[:, :2048]^T   (mask == K-truncation; G symmetric)
//   T1 = P @ G ;  A2 = T1 @ Q ;  out = H + (A2 @ H) / 2048
// bf16 mma.sync (fp32 accum) with ldmatrix fragment loads, SW128 smem,
// 128x128 CTA tiles, 3-stage cp.async pipeline.
// (tcgen05 is unavailable: harness emits compute_103 PTX, no 'a' feature.)

#define BATCH 16
#define D_REAL 257
#define N_REAL 2049
#define HSTR   (257L * 2049L)

#define DP 384      // padded d as M/N (mult of 128)
#define DK 320      // padded d as K   (mult of 64)
#define NP 2176     // padded n        (mult of 128)
#define NSTG 3
#define BK 64       // K per chunk = 128 B per row = SW128 atom

__device__ __align__(256) __nv_bfloat16 g_Hb [BATCH * DP * NP];
__device__ __align__(256) __nv_bfloat16 g_HbT[BATCH * NP * DP];
__device__ __align__(256) __nv_bfloat16 g_Pb [DP * DK];
__device__ __align__(256) __nv_bfloat16 g_QbT[DP * DK];
__device__ __align__(256) __nv_bfloat16 g_S1 [BATCH * DP * DP];
__device__ __align__(256) __nv_bfloat16 g_S2 [BATCH * DP * DP];

// ---------------------------------------------------------------- helpers

__device__ __forceinline__ uint32_t smem_u32(const void* p) {
    uint32_t a;
    asm("{ .reg .u64 t; cvta.to.shared.u64 t, %1; cvt.u32.u64 %0, t; }"
        : "=r"(a) : "l"(p));
    return a;
}

__device__ __forceinline__ void cp16s(uint32_t dst, const void* src) {
    asm volatile("cp.async.cg.shared.global [%0], [%1], 16;\n" :: "r"(dst), "l"(src));
}

#define SWZ(off) ((off) ^ (((off) >> 3) & 0x70))

__device__ __forceinline__ void ldm_x4(uint32_t* r, uint32_t addr) {
    asm volatile("ldmatrix.sync.aligned.m8n8.x4.shared.b16 {%0,%1,%2,%3}, [%4];"
                 : "=r"(r[0]), "=r"(r[1]), "=r"(r[2]), "=r"(r[3]) : "r"(addr));
}

__device__ __forceinline__ void mma16816(float* d, const uint32_t* a,
                                         uint32_t b0, uint32_t b1) {
    asm volatile(
        "mma.sync.aligned.m16n8k16.row.col.f32.bf16.bf16.f32 "
        "{%0,%1,%2,%3}, {%4,%5,%6,%7}, {%8,%9}, {%0,%1,%2,%3};"
        : "+f"(d[0]), "+f"(d[1]), "+f"(d[2]), "+f"(d[3])
        : "r"(a[0]), "r"(a[1]), "r"(a[2]), "r"(a[3]), "r"(b0), "r"(b1));
}

// ---------------------------------------------------------------- converts

__global__ void conv_H(const float* __restrict__ H,
                       __nv_bfloat16* __restrict__ Hb,
                       __nv_bfloat16* __restrict__ HbT)
{
    __shared__ float t[32][33];
    const int b  = blockIdx.z;
    const int n0 = blockIdx.x * 32;
    const int d0 = blockIdx.y * 32;
    const int tx = threadIdx.x, ty = threadIdx.y;
    const float* Hp = H + (long)b * HSTR;

    #pragma unroll
    for (int i = 0; i < 4; i++) {
        int d = d0 + ty + i * 8, n = n0 + tx;
        float v = 0.f;
        if (d < D_REAL && n < N_REAL) v = Hp[(long)d * N_REAL + n];
        t[ty + i * 8][tx] = v;
    }
    __syncthreads();
    __nv_bfloat16* Hbp  = Hb  + (long)b * DP * NP;
    __nv_bfloat16* HbTp = HbT + (long)b * NP * DP;
    #pragma unroll
    for (int i = 0; i < 4; i++) {
        int d = d0 + ty + i * 8, n = n0 + tx;
        Hbp[(long)d * NP + n] = __float2bfloat16(t[ty + i * 8][tx]);
    }
    #pragma unroll
    for (int i = 0; i < 4; i++) {
        int n = n0 + ty + i * 8, d = d0 + tx;
        HbTp[(long)n * DP + d] = __float2bfloat16(t[tx][ty + i * 8]);
    }
}

__global__ void conv_P(const float* __restrict__ P, __nv_bfloat16* __restrict__ Pb)
{
    int idx = blockIdx.x * blockDim.x + threadIdx.x;
    if (idx >= DP * DK) return;
    int r = idx / DK, c = idx % DK;
    Pb[idx] = __float2bfloat16((r < D_REAL && c < D_REAL) ? P[r * D_REAL + c] : 0.f);
}

__global__ void conv_QT(const float* __restrict__ Q, __nv_bfloat16* __restrict__ QbT)
{
    int idx = blockIdx.x * blockDim.x + threadIdx.x;
    if (idx >= DP * DK) return;
    int n = idx / DK, k = idx % DK;
    QbT[idx] = __float2bfloat16((n < D_REAL && k < D_REAL) ? Q[k * D_REAL + n] : 0.f);
}

// ---------------------------------------------------------------- GEMM NT

// C[M,N] = scale * A[M,K] @ B[N,K]^T. 128x128 CTA tile, warp tile 64x32.
// EPI=0: bf16 to Cb (padded). EPI=1: fp32 out = Hadd + acc*scale, guarded.
template<int EPI>
__global__ void __launch_bounds__(256, 2)
gemm_nt(const __nv_bfloat16* __restrict__ A,
        const __nv_bfloat16* __restrict__ B,
        __nv_bfloat16* __restrict__ Cb,
        float* __restrict__ Cf,
        const float* __restrict__ Hadd,
        int K, int lda, int ldb, int ldc,
        long sA, long sB, long sC, float scale)
{
    extern __shared__ __align__(1024) char dyn[];
    const int bz = blockIdx.z;
    A += (long)bz * sA;
    B += (long)bz * sB;
    const int bm = blockIdx.y * 128;
    const int bn = blockIdx.x * 128;
    const int tid  = threadIdx.x;
    const int lane = tid & 31;
    const int wid  = tid >> 5;
    const int g    = lane >> 2;
    const int tig  = lane & 3;
    const int wm   = (wid & 1) * 64;     // 2 warps over m
    const int wn   = (wid >> 1) * 32;    // 4 warps over n

    const uint32_t base = smem_u32(dyn);  // [NSTG][A:16KB | B:16KB]

    float acc[4][4][4];
    #pragma unroll
    for (int i = 0; i < 4; i++)
        #pragma unroll
        for (int j = 0; j < 4; j++)
            #pragma unroll
            for (int r = 0; r < 4; r++) acc[i][j][r] = 0.f;

    // ldmatrix per-lane geometry (x4):
    // A: lanes 0-15 -> rows 0-15 at k0, lanes 16-31 -> rows 0-15 at k+8
    // B: lanes 0-7 -> n+0..7 @k0, 8-15 -> same @k8, 16-23 -> n+8..15 @k0, 24-31 @k8
    const uint32_t swx      = (uint32_t)((lane & 7) << 4);
    const uint32_t a_rowoff = (uint32_t)(wm + (lane & 15)) * 128;
    const uint32_t a_koff   = (uint32_t)((lane >> 4) * 16);
    const uint32_t b_rowoff = (uint32_t)(wn + (lane & 7) + ((lane >> 4) & 1) * 8) * 128;
    const uint32_t b_koff   = (uint32_t)(((lane >> 3) & 1) * 16);

    auto load_chunk = [&](int c) {
        const int st = c % NSTG;
        const uint32_t ab = base + st * 32768;
        const uint32_t bb = ab + 16384;
        const int k0 = c * BK;
        #pragma unroll
        for (int i = 0; i < 4; i++) {
            int ch  = tid + i * 256;
            int row = ch >> 3;
            int q   = ch & 7;
            uint32_t off = SWZ(row * 128 + q * 16);
            cp16s(ab + off, A + (long)(bm + row) * lda + k0 + q * 8);
            cp16s(bb + off, B + (long)(bn + row) * ldb + k0 + q * 8);
        }
        asm volatile("cp.async.commit_group;");
    };

    const int nk = K / BK;   // >= NSTG at every call site
    load_chunk(0);
    load_chunk(1);

    for (int kt = 0; kt < nk; kt++) {
        if (kt + 2 < nk) load_chunk(kt + 2);
        else asm volatile("cp.async.commit_group;");
        asm volatile("cp.async.wait_group %0;" :: "n"(NSTG - 1));
        __syncthreads();

        const uint32_t ab = base + (kt % NSTG) * 32768;
        const uint32_t bb = ab + 16384;

        #pragma unroll
        for (int kk = 0; kk < 4; kk++) {               // 4 x k16 per BK=64
            uint32_t af[4][4], bf[2][4];
            #pragma unroll
            for (int mi = 0; mi < 4; mi++)
                ldm_x4(af[mi], ab + a_rowoff + mi * 2048
                               + ((uint32_t)(kk * 32) + a_koff ^ swx));
            #pragma unroll
            for (int p = 0; p < 2; p++)
                ldm_x4(bf[p], bb + b_rowoff + p * 2048
                              + ((uint32_t)(kk * 32) + b_koff ^ swx));
            #pragma unroll
            for (int mi = 0; mi < 4; mi++)
                #pragma unroll
                for (int ni = 0; ni < 4; ni++)
                    mma16816(acc[mi][ni], af[mi],
                             bf[ni >> 1][(ni & 1) * 2], bf[ni >> 1][(ni & 1) * 2 + 1]);
        }
        __syncthreads();
    }

    if (EPI == 0) {
        __nv_bfloat16* Cp = Cb + (long)bz * sC;
        #pragma unroll
        for (int mi = 0; mi < 4; mi++) {
            int r0 = bm + wm + mi * 16 + g;
            #pragma unroll
            for (int ni = 0; ni < 4; ni++) {
                int c = bn + wn + ni * 8 + tig * 2;
                __nv_bfloat162 v01, v23;
                v01.x = __float2bfloat16(acc[mi][ni][0] * scale);
                v01.y = __float2bfloat16(acc[mi][ni][1] * scale);
                v23.x = __float2bfloat16(acc[mi][ni][2] * scale);
                v23.y = __float2bfloat16(acc[mi][ni][3] * scale);
                *(__nv_bfloat162*)&Cp[(long)r0 * ldc + c]       = v01;
                *(__nv_bfloat162*)&Cp[(long)(r0 + 8) * ldc + c] = v23;
            }
        }
    } else {
        const float* Hp = Hadd + (long)bz * HSTR;
        float*       Op = Cf   + (long)bz * HSTR;
        #pragma unroll
        for (int mi = 0; mi < 4; mi++) {
            int r0 = bm + wm + mi * 16 + g;
            #pragma unroll
            for (int ni = 0; ni < 4; ni++) {
                int c = bn + wn + ni * 8 + tig * 2;
                #pragma unroll
                for (int half = 0; half < 2; half++) {
                    int r = r0 + half * 8;
                    if (r < D_REAL) {
                        if (c < N_REAL) {
                            long idx = (long)r * N_REAL + c;
                            Op[idx] = Hp[idx] + acc[mi][ni][half * 2 + 0] * scale;
                        }
                        if (c + 1 < N_REAL) {
                            long idx = (long)r * N_REAL + c + 1;
                            Op[idx] = Hp[idx] + acc[mi][ni][half * 2 + 1] * scale;
                        }
                    }
                }
            }
        }
    }
}

// ---------------------------------------------------------------- launch

extern "C" void kernel_launch(void* const* d_in, const int* in_sizes, int n_in,
                              void* d_out, int out_size)
{
    const float* H = (const float*)d_in[0];
    const float* P = (const float*)d_in[1];
    const float* Q = (const float*)d_in[2];
    float* out = (float*)d_out;

    void *pHb, *pHbT, *pPb, *pQbT, *pS1, *pS2;
    cudaGetSymbolAddress(&pHb,  g_Hb);
    cudaGetSymbolAddress(&pHbT, g_HbT);
    cudaGetSymbolAddress(&pPb,  g_Pb);
    cudaGetSymbolAddress(&pQbT, g_QbT);
    cudaGetSymbolAddress(&pS1,  g_S1);
    cudaGetSymbolAddress(&pS2,  g_S2);
    __nv_bfloat16* Hb  = (__nv_bfloat16*)pHb;
    __nv_bfloat16* HbT = (__nv_bfloat16*)pHbT;
    __nv_bfloat16* Pb  = (__nv_bfloat16*)pPb;
    __nv_bfloat16* QbT = (__nv_bfloat16*)pQbT;
    __nv_bfloat16* S1  = (__nv_bfloat16*)pS1;
    __nv_bfloat16* S2  = (__nv_bfloat16*)pS2;

    const long sHN = (long)DP * NP;
    const long sNT = (long)NP * DP;
    const long sDD = (long)DP * DP;

    conv_H <<<dim3(NP / 32, DP / 32, BATCH), dim3(32, 8)>>>(H, Hb, HbT);
    conv_P <<<(DP * DK + 255) / 256, 256>>>(P, Pb);
    conv_QT<<<(DP * DK + 255) / 256, 256>>>(Q, QbT);

    const int smem = NSTG * 32768;   // 96 KB
    cudaFuncSetAttribute(gemm_nt<0>, cudaFuncAttributeMaxDynamicSharedMemorySize, smem);
    cudaFuncSetAttribute(gemm_nt<1>, cudaFuncAttributeMaxDynamicSharedMemorySize, smem);

    dim3 blk(256);
    dim3 gSq  (DP / 128, DP / 128, BATCH);   // 3 x 3 x 16 = 144
    dim3 gWide(NP / 128, DP / 128, BATCH);   // 17 x 3 x 16 = 816

    // 1) G = H[:, :2048] @ H[:, :2048]^T
    gemm_nt<0><<<gSq, blk, smem>>>(Hb, Hb, S1, nullptr, nullptr,
                                   2048, NP, NP, DP, sHN, sHN, sDD, 1.f);
    // 2) T1 = P @ G  (G symmetric -> B-operand directly)
    gemm_nt<0><<<gSq, blk, smem>>>(Pb, S1, S2, nullptr, nullptr,
                                   DK, DK, DP, DP, 0, sDD, sDD, 1.f);
    // 3) A2 = T1 @ Q
    gemm_nt<0><<<gSq, blk, smem>>>(S2, QbT, S1, nullptr, nullptr,
                                   DK, DP, DK, DP, sDD, 0, sDD, 1.f);
    // 4) out = H + (A2 @ H) / 2048
    gemm_nt<1><<<gWide, blk, smem>>>(S1, HbT, nullptr, out, H,
                                     DK, DP, DP, 0, sDD, sNT, 0, 1.f / 2048.f);
}